// round 1
// baseline (speedup 1.0000x reference)
#include <cuda_runtime.h>
#include <math.h>

// Shapes (fixed for this problem)
#define BB  1024   // batch
#define PP  256    // patches
#define DD  1024   // dino dim
#define DC  512    // clip dim

// Scratch (no allocation allowed)
__device__ float g_t [BB * DD];   // tanh(text @ W^T + b)
__device__ float g_tn[BB * DD];   // normalized t
__device__ float g_vb[BB * DD];   // normalized best patch per batch

// ---------------------------------------------------------------------------
// Tiled NT GEMM: C[m,n] = op( sum_k A[m,k] * Bm[n,k] (+ bias[n]) )
// A: [M,K] row-major, Bm: [N,K] row-major, M=N=1024 fixed, K template.
// 64x64 block tile, 16x16 threads, 4x4 micro-tile, k-tile 16.
// ---------------------------------------------------------------------------
template<int K, bool TANH>
__global__ void __launch_bounds__(256)
gemm_nt_kernel(const float* __restrict__ A, const float* __restrict__ Bm,
               const float* __restrict__ bias, float* __restrict__ C)
{
    __shared__ float As[16][68];   // [k][m], padded: 68*4B = 272B row (16B aligned)
    __shared__ float Bs[16][68];   // [k][n]

    const int tx = threadIdx.x;    // 0..15 -> n
    const int ty = threadIdx.y;    // 0..15 -> m
    const int tid = ty * 16 + tx;
    const int m0 = blockIdx.y * 64;
    const int n0 = blockIdx.x * 64;

    const int lr = tid >> 2;       // 0..63 : row within tile
    const int lc = tid & 3;        // 0..3  : float4 column within k-tile

    float acc[4][4];
    #pragma unroll
    for (int i = 0; i < 4; i++)
        #pragma unroll
        for (int j = 0; j < 4; j++) acc[i][j] = 0.f;

    for (int kk = 0; kk < K; kk += 16) {
        float4 a = *(const float4*)&A [(size_t)(m0 + lr) * K + kk + lc * 4];
        float4 b = *(const float4*)&Bm[(size_t)(n0 + lr) * K + kk + lc * 4];
        As[lc*4+0][lr] = a.x; As[lc*4+1][lr] = a.y;
        As[lc*4+2][lr] = a.z; As[lc*4+3][lr] = a.w;
        Bs[lc*4+0][lr] = b.x; Bs[lc*4+1][lr] = b.y;
        Bs[lc*4+2][lr] = b.z; Bs[lc*4+3][lr] = b.w;
        __syncthreads();

        #pragma unroll
        for (int k = 0; k < 16; k++) {
            float4 av = *(const float4*)&As[k][ty * 4];
            float4 bv = *(const float4*)&Bs[k][tx * 4];
            acc[0][0] += av.x * bv.x; acc[0][1] += av.x * bv.y;
            acc[0][2] += av.x * bv.z; acc[0][3] += av.x * bv.w;
            acc[1][0] += av.y * bv.x; acc[1][1] += av.y * bv.y;
            acc[1][2] += av.y * bv.z; acc[1][3] += av.y * bv.w;
            acc[2][0] += av.z * bv.x; acc[2][1] += av.z * bv.y;
            acc[2][2] += av.z * bv.z; acc[2][3] += av.z * bv.w;
            acc[3][0] += av.w * bv.x; acc[3][1] += av.w * bv.y;
            acc[3][2] += av.w * bv.z; acc[3][3] += av.w * bv.w;
        }
        __syncthreads();
    }

    #pragma unroll
    for (int i = 0; i < 4; i++) {
        const int m = m0 + ty * 4 + i;
        #pragma unroll
        for (int j = 0; j < 4; j++) {
            const int n = n0 + tx * 4 + j;
            float v = acc[i][j];
            if (TANH) v = tanhf(v + bias[n]);
            C[(size_t)m * 1024 + n] = v;
        }
    }
}

// ---------------------------------------------------------------------------
// Row-wise L2 normalize: out[b,:] = in[b,:] / max(||in[b,:]||, 1e-12)
// 1 block per row of 1024 floats, 256 threads (1 float4 each).
// ---------------------------------------------------------------------------
__global__ void __launch_bounds__(256)
norm_rows_kernel(const float* __restrict__ in, float* __restrict__ out)
{
    const int b = blockIdx.x;
    const int t = threadIdx.x;
    const int lane = t & 31, warp = t >> 5;
    const float4* i4 = (const float4*)(in + (size_t)b * DD);
    float4 v = i4[t];
    float ss = v.x*v.x + v.y*v.y + v.z*v.z + v.w*v.w;
    #pragma unroll
    for (int o = 16; o; o >>= 1) ss += __shfl_xor_sync(0xffffffffu, ss, o);

    __shared__ float sred[8];
    __shared__ float sinv;
    if (lane == 0) sred[warp] = ss;
    __syncthreads();
    if (t == 0) {
        float tot = 0.f;
        #pragma unroll
        for (int w = 0; w < 8; w++) tot += sred[w];
        sinv = 1.0f / fmaxf(sqrtf(tot), 1e-12f);
    }
    __syncthreads();
    const float inv = sinv;
    float4* o4 = (float4*)(out + (size_t)b * DD);
    v.x *= inv; v.y *= inv; v.z *= inv; v.w *= inv;
    o4[t] = v;
}

// ---------------------------------------------------------------------------
// Main kernel: per batch b, sims[p] = dot(tn[b], v[b,p]) / ||v[b,p]||,
// argmax over p (first-max tie-break), write vb[b,:] = v[b,idx,:]/||.||.
// 1 block per b, 8 warps, each warp owns 32 contiguous patches.
// Each lane owns a fixed D-slice: float4 indices lane+32k, k=0..7 (tn cached
// in registers). 8 independent global float4 loads per patch -> good MLP.
// ---------------------------------------------------------------------------
__global__ void __launch_bounds__(256)
sims_argmax_kernel(const float* __restrict__ visual,
                   const float* __restrict__ tn,
                   float* __restrict__ vb)
{
    const int b = blockIdx.x;
    const int lane = threadIdx.x & 31;
    const int warp = threadIdx.x >> 5;

    const float4* v4 = (const float4*)(visual + (size_t)b * PP * DD);
    const float4* t4 = (const float4*)(tn + (size_t)b * DD);

    float4 tr[8];
    #pragma unroll
    for (int k = 0; k < 8; k++) tr[k] = t4[lane + 32 * k];

    float best = -1e30f; int bidx = 0; float bss = 1.f;

    for (int pp = 0; pp < 32; pp++) {
        const int p = warp * 32 + pp;
        const float4* row = v4 + (size_t)p * (DD / 4);
        float dot = 0.f, ss = 0.f;
        #pragma unroll
        for (int k = 0; k < 8; k++) {
            float4 v = row[lane + 32 * k];
            dot += v.x * tr[k].x + v.y * tr[k].y + v.z * tr[k].z + v.w * tr[k].w;
            ss  += v.x * v.x + v.y * v.y + v.z * v.z + v.w * v.w;
        }
        #pragma unroll
        for (int o = 16; o; o >>= 1) {
            dot += __shfl_xor_sync(0xffffffffu, dot, o);
            ss  += __shfl_xor_sync(0xffffffffu, ss,  o);
        }
        const float sim = dot / fmaxf(sqrtf(ss), 1e-12f);
        if (sim > best) { best = sim; bidx = p; bss = ss; }   // strict > keeps first max
    }

    __shared__ float sval[8]; __shared__ int sidx[8]; __shared__ float ssum[8];
    __shared__ int s_p; __shared__ float s_inv;
    if (lane == 0) { sval[warp] = best; sidx[warp] = bidx; ssum[warp] = bss; }
    __syncthreads();
    if (threadIdx.x == 0) {
        float bv = sval[0]; int bi = sidx[0]; float bs = ssum[0];
        #pragma unroll
        for (int w = 1; w < 8; w++) {
            if (sval[w] > bv || (sval[w] == bv && sidx[w] < bi)) {
                bv = sval[w]; bi = sidx[w]; bs = ssum[w];
            }
        }
        s_p = bi;
        s_inv = 1.0f / fmaxf(sqrtf(bs), 1e-12f);
    }
    __syncthreads();

    const int p = s_p;
    const float inv = s_inv;
    const float4* row = v4 + (size_t)p * (DD / 4);
    float4* ob = (float4*)(vb + (size_t)b * DD);
    for (int i = threadIdx.x; i < DD / 4; i += 256) {
        float4 v = row[i];           // just-read row: L2 hit
        v.x *= inv; v.y *= inv; v.z *= inv; v.w *= inv;
        ob[i] = v;
    }
}

// ---------------------------------------------------------------------------
extern "C" void kernel_launch(void* const* d_in, const int* in_sizes, int n_in,
                              void* d_out, int out_size)
{
    const float* visual = (const float*)d_in[0];   // [1024, 256, 1024]
    const float* text   = (const float*)d_in[1];   // [1024, 512]
    const float* W      = (const float*)d_in[2];   // [1024, 512]
    const float* bias   = (const float*)d_in[3];   // [1024]
    float* out = (float*)d_out;                    // [1024, 1024]

    float *p_t, *p_tn, *p_vb;
    cudaGetSymbolAddress((void**)&p_t,  g_t);
    cudaGetSymbolAddress((void**)&p_tn, g_tn);
    cudaGetSymbolAddress((void**)&p_vb, g_vb);

    dim3 gblk(16, 16), gthr(16, 16);

    // 1) t = tanh(text @ W^T + b)
    gemm_nt_kernel<DC, true><<<gblk, gthr>>>(text, W, bias, p_t);
    // 2) tn = l2norm(t)
    norm_rows_kernel<<<BB, 256>>>(p_t, p_tn);
    // 3) per-b argmax over patches + gather normalized best patch
    sims_argmax_kernel<<<BB, 256>>>(visual, p_tn, p_vb);
    // 4) out = tn @ vb^T
    gemm_nt_kernel<DD, false><<<gblk, gthr>>>(p_tn, p_vb, nullptr, out);
}

// round 5
// speedup vs baseline: 1.1152x; 1.1152x over previous
#include <cuda_runtime.h>
#include <math.h>
#include <stdint.h>

// Shapes (fixed for this problem)
#define BB  1024   // batch
#define PP  256    // patches
#define DD  1024   // dino dim
#define DC  512    // clip dim

// Scratch (no allocation allowed)
__device__ float g_t [BB * DD];   // tanh(text @ W^T + b)
__device__ float g_tn[BB * DD];   // normalized t
__device__ float g_vb[BB * DD];   // normalized best patch per batch

// ---------------------------------------------------------------------------
// Tiled NT GEMM (fp32 SIMT) — used only for GEMM1 (argmax-critical precision)
// C[m,n] = tanh( sum_k A[m,k]*Bm[n,k] + bias[n] )
// ---------------------------------------------------------------------------
template<int K, bool TANH>
__global__ void __launch_bounds__(256)
gemm_nt_kernel(const float* __restrict__ A, const float* __restrict__ Bm,
               const float* __restrict__ bias, float* __restrict__ C)
{
    __shared__ float As[16][68];
    __shared__ float Bs[16][68];

    const int tx = threadIdx.x;
    const int ty = threadIdx.y;
    const int tid = ty * 16 + tx;
    const int m0 = blockIdx.y * 64;
    const int n0 = blockIdx.x * 64;

    const int lr = tid >> 2;
    const int lc = tid & 3;

    float acc[4][4];
    #pragma unroll
    for (int i = 0; i < 4; i++)
        #pragma unroll
        for (int j = 0; j < 4; j++) acc[i][j] = 0.f;

    for (int kk = 0; kk < K; kk += 16) {
        float4 a = *(const float4*)&A [(size_t)(m0 + lr) * K + kk + lc * 4];
        float4 b = *(const float4*)&Bm[(size_t)(n0 + lr) * K + kk + lc * 4];
        As[lc*4+0][lr] = a.x; As[lc*4+1][lr] = a.y;
        As[lc*4+2][lr] = a.z; As[lc*4+3][lr] = a.w;
        Bs[lc*4+0][lr] = b.x; Bs[lc*4+1][lr] = b.y;
        Bs[lc*4+2][lr] = b.z; Bs[lc*4+3][lr] = b.w;
        __syncthreads();

        #pragma unroll
        for (int k = 0; k < 16; k++) {
            float4 av = *(const float4*)&As[k][ty * 4];
            float4 bv = *(const float4*)&Bs[k][tx * 4];
            acc[0][0] += av.x * bv.x; acc[0][1] += av.x * bv.y;
            acc[0][2] += av.x * bv.z; acc[0][3] += av.x * bv.w;
            acc[1][0] += av.y * bv.x; acc[1][1] += av.y * bv.y;
            acc[1][2] += av.y * bv.z; acc[1][3] += av.y * bv.w;
            acc[2][0] += av.z * bv.x; acc[2][1] += av.z * bv.y;
            acc[2][2] += av.z * bv.z; acc[2][3] += av.z * bv.w;
            acc[3][0] += av.w * bv.x; acc[3][1] += av.w * bv.y;
            acc[3][2] += av.w * bv.z; acc[3][3] += av.w * bv.w;
        }
        __syncthreads();
    }

    #pragma unroll
    for (int i = 0; i < 4; i++) {
        const int m = m0 + ty * 4 + i;
        #pragma unroll
        for (int j = 0; j < 4; j++) {
            const int n = n0 + tx * 4 + j;
            float v = acc[i][j];
            if (TANH) v = tanhf(v + bias[n]);
            C[(size_t)m * 1024 + n] = v;
        }
    }
}

// ---------------------------------------------------------------------------
// Row-wise L2 normalize
// ---------------------------------------------------------------------------
__global__ void __launch_bounds__(256)
norm_rows_kernel(const float* __restrict__ in, float* __restrict__ out)
{
    const int b = blockIdx.x;
    const int t = threadIdx.x;
    const int lane = t & 31, warp = t >> 5;
    const float4* i4 = (const float4*)(in + (size_t)b * DD);
    float4 v = i4[t];
    float ss = v.x*v.x + v.y*v.y + v.z*v.z + v.w*v.w;
    #pragma unroll
    for (int o = 16; o; o >>= 1) ss += __shfl_xor_sync(0xffffffffu, ss, o);

    __shared__ float sred[8];
    __shared__ float sinv;
    if (lane == 0) sred[warp] = ss;
    __syncthreads();
    if (t == 0) {
        float tot = 0.f;
        #pragma unroll
        for (int w = 0; w < 8; w++) tot += sred[w];
        sinv = 1.0f / fmaxf(sqrtf(tot), 1e-12f);
    }
    __syncthreads();
    const float inv = sinv;
    float4* o4 = (float4*)(out + (size_t)b * DD);
    v.x *= inv; v.y *= inv; v.z *= inv; v.w *= inv;
    o4[t] = v;
}

// ---------------------------------------------------------------------------
// sims + argmax + gather (HBM-bound; reads 1 GB once)
// ---------------------------------------------------------------------------
__global__ void __launch_bounds__(256)
sims_argmax_kernel(const float* __restrict__ visual,
                   const float* __restrict__ tn,
                   float* __restrict__ vb)
{
    const int b = blockIdx.x;
    const int lane = threadIdx.x & 31;
    const int warp = threadIdx.x >> 5;

    const float4* v4 = (const float4*)(visual + (size_t)b * PP * DD);
    const float4* t4 = (const float4*)(tn + (size_t)b * DD);

    float4 tr[8];
    #pragma unroll
    for (int k = 0; k < 8; k++) tr[k] = t4[lane + 32 * k];

    float best = -1e30f; int bidx = 0; float bss = 1.f;

    for (int pp = 0; pp < 32; pp++) {
        const int p = warp * 32 + pp;
        const float4* row = v4 + (size_t)p * (DD / 4);
        float dot = 0.f, ss = 0.f;
        #pragma unroll
        for (int k = 0; k < 8; k++) {
            float4 v = row[lane + 32 * k];
            dot += v.x * tr[k].x + v.y * tr[k].y + v.z * tr[k].z + v.w * tr[k].w;
            ss  += v.x * v.x + v.y * v.y + v.z * v.z + v.w * v.w;
        }
        #pragma unroll
        for (int o = 16; o; o >>= 1) {
            dot += __shfl_xor_sync(0xffffffffu, dot, o);
            ss  += __shfl_xor_sync(0xffffffffu, ss,  o);
        }
        const float sim = dot / fmaxf(sqrtf(ss), 1e-12f);
        if (sim > best) { best = sim; bidx = p; bss = ss; }
    }

    __shared__ float sval[8]; __shared__ int sidx[8]; __shared__ float ssum[8];
    __shared__ int s_p; __shared__ float s_inv;
    if (lane == 0) { sval[warp] = best; sidx[warp] = bidx; ssum[warp] = bss; }
    __syncthreads();
    if (threadIdx.x == 0) {
        float bv = sval[0]; int bi = sidx[0]; float bs = ssum[0];
        #pragma unroll
        for (int w = 1; w < 8; w++) {
            if (sval[w] > bv || (sval[w] == bv && sidx[w] < bi)) {
                bv = sval[w]; bi = sidx[w]; bs = ssum[w];
            }
        }
        s_p = bi;
        s_inv = 1.0f / fmaxf(sqrtf(bs), 1e-12f);
    }
    __syncthreads();

    const int p = s_p;
    const float inv = s_inv;
    const float4* row = v4 + (size_t)p * (DD / 4);
    float4* ob = (float4*)(vb + (size_t)b * DD);
    for (int i = threadIdx.x; i < DD / 4; i += 256) {
        float4 v = row[i];
        v.x *= inv; v.y *= inv; v.z *= inv; v.w *= inv;
        ob[i] = v;
    }
}

// ===========================================================================
// GEMM2 via mma.sync tf32 (sm_80+ PTX — assembles at base sm_103 target).
// C[1024,1024] = A[1024,1024] @ B[1024,1024]^T, both row-major [*,K] (NT =
// native row.col for mma.sync). Block 64x64, 2x2 warps (warp tile 32x32),
// K-tile 32. tf32 conversion (cvt.rna) in registers before STS.
// Smem pitch 36 floats: 144B rows (16B aligned) and conflict-free
// quad-pattern fragment loads.
// ===========================================================================
__device__ __forceinline__ uint32_t f2tf32(float f) {
    uint32_t u;
    asm("cvt.rna.tf32.f32 %0, %1;" : "=r"(u) : "f"(f));
    return u;
}

__global__ void __launch_bounds__(128)
gemm_mma_tf32(const float* __restrict__ A, const float* __restrict__ Bm,
              float* __restrict__ C)
{
    __shared__ uint32_t As[64][36];   // [m][k], pitch 36 (144B, 16B-aligned)
    __shared__ uint32_t Bs[64][36];   // [n][k]

    const int tid  = threadIdx.x;
    const int lane = tid & 31;
    const int warp = tid >> 5;        // 0..3
    const int wm   = warp >> 1;       // 0..1 -> m offset 32*wm
    const int wn   = warp & 1;        // 0..1 -> n offset 32*wn
    const int gid  = lane >> 2;       // 0..7
    const int tig  = lane & 3;        // 0..3

    const int m0 = blockIdx.y * 64;
    const int n0 = blockIdx.x * 64;

    // gmem load mapping: 64 rows x 32 cols = 4 float4 per thread
    const int lr = tid >> 3;          // 0..15
    const int lc = tid & 7;           // 0..7 (float4 index)

    float c[2][4][4];                 // [m-tile][n-tile][frag]
    #pragma unroll
    for (int i = 0; i < 2; i++)
        #pragma unroll
        for (int j = 0; j < 4; j++)
            #pragma unroll
            for (int q = 0; q < 4; q++) c[i][j][q] = 0.f;

    for (int kk = 0; kk < DD; kk += 32) {
        #pragma unroll
        for (int i = 0; i < 4; i++) {
            const int r = lr + i * 16;
            float4 a = *(const float4*)(A  + (size_t)(m0 + r) * DD + kk + lc * 4);
            float4 b = *(const float4*)(Bm + (size_t)(n0 + r) * DD + kk + lc * 4);
            *(uint4*)&As[r][lc * 4] = make_uint4(f2tf32(a.x), f2tf32(a.y),
                                                 f2tf32(a.z), f2tf32(a.w));
            *(uint4*)&Bs[r][lc * 4] = make_uint4(f2tf32(b.x), f2tf32(b.y),
                                                 f2tf32(b.z), f2tf32(b.w));
        }
        __syncthreads();

        #pragma unroll
        for (int k8 = 0; k8 < 4; k8++) {
            const int k0 = k8 * 8;

            uint32_t af[2][4];
            #pragma unroll
            for (int mi = 0; mi < 2; mi++) {
                const int row = wm * 32 + mi * 16 + gid;
                af[mi][0] = As[row    ][k0 + tig];
                af[mi][1] = As[row + 8][k0 + tig];
                af[mi][2] = As[row    ][k0 + tig + 4];
                af[mi][3] = As[row + 8][k0 + tig + 4];
            }
            uint32_t bf[4][2];
            #pragma unroll
            for (int nj = 0; nj < 4; nj++) {
                const int col = wn * 32 + nj * 8 + gid;
                bf[nj][0] = Bs[col][k0 + tig];
                bf[nj][1] = Bs[col][k0 + tig + 4];
            }

            #pragma unroll
            for (int mi = 0; mi < 2; mi++)
                #pragma unroll
                for (int nj = 0; nj < 4; nj++)
                    asm volatile(
                        "mma.sync.aligned.m16n8k8.row.col.f32.tf32.tf32.f32 "
                        "{%0,%1,%2,%3}, {%4,%5,%6,%7}, {%8,%9}, {%0,%1,%2,%3};"
                        : "+f"(c[mi][nj][0]), "+f"(c[mi][nj][1]),
                          "+f"(c[mi][nj][2]), "+f"(c[mi][nj][3])
                        : "r"(af[mi][0]), "r"(af[mi][1]),
                          "r"(af[mi][2]), "r"(af[mi][3]),
                          "r"(bf[nj][0]), "r"(bf[nj][1]));
        }
        __syncthreads();
    }

    // Epilogue: c0,c1 -> (row, 2tig..2tig+1); c2,c3 -> (row+8, same cols)
    #pragma unroll
    for (int mi = 0; mi < 2; mi++) {
        const int row = m0 + wm * 32 + mi * 16 + gid;
        #pragma unroll
        for (int nj = 0; nj < 4; nj++) {
            const int col = n0 + wn * 32 + nj * 8 + tig * 2;
            *(float2*)(C + (size_t)row * DD + col) =
                make_float2(c[mi][nj][0], c[mi][nj][1]);
            *(float2*)(C + (size_t)(row + 8) * DD + col) =
                make_float2(c[mi][nj][2], c[mi][nj][3]);
        }
    }
}

// ---------------------------------------------------------------------------
extern "C" void kernel_launch(void* const* d_in, const int* in_sizes, int n_in,
                              void* d_out, int out_size)
{
    const float* visual = (const float*)d_in[0];   // [1024, 256, 1024]
    const float* text   = (const float*)d_in[1];   // [1024, 512]
    const float* W      = (const float*)d_in[2];   // [1024, 512]
    const float* bias   = (const float*)d_in[3];   // [1024]
    float* out = (float*)d_out;                    // [1024, 1024]

    float *p_t, *p_tn, *p_vb;
    cudaGetSymbolAddress((void**)&p_t,  g_t);
    cudaGetSymbolAddress((void**)&p_tn, g_tn);
    cudaGetSymbolAddress((void**)&p_vb, g_vb);

    dim3 gblk(16, 16), gthr(16, 16);

    // 1) t = tanh(text @ W^T + b)   (fp32: feeds the argmax, keep exact)
    gemm_nt_kernel<DC, true><<<gblk, gthr>>>(text, W, bias, p_t);
    // 2) tn = l2norm(t)
    norm_rows_kernel<<<BB, 256>>>(p_t, p_tn);
    // 3) per-b argmax over patches + gather normalized best patch
    sims_argmax_kernel<<<BB, 256>>>(visual, p_tn, p_vb);
    // 4) out = tn @ vb^T  (tensor cores, tf32 mma.sync)
    gemm_mma_tf32<<<dim3(16, 16), 128>>>(p_tn, p_vb, out);
}

// round 6
// speedup vs baseline: 1.3048x; 1.1700x over previous
#include <cuda_runtime.h>
#include <math.h>
#include <stdint.h>

// Shapes (fixed for this problem)
#define BB  1024   // batch
#define PP  256    // patches
#define DD  1024   // dino dim
#define DC  512    // clip dim

// Scratch (no allocation allowed)
__device__ float g_tn[BB * DD];   // normalized t
__device__ float g_t [BB * DD];   // tanh(text @ W^T + b)
__device__ float g_vb[BB * DD];   // normalized best patch per batch

__device__ __forceinline__ uint32_t f2tf32(float f) {
    uint32_t u;
    asm("cvt.rna.tf32.f32 %0, %1;" : "=r"(u) : "f"(f));
    return u;
}

// ===========================================================================
// Unified tf32 mma.sync NT GEMM: C[m,n] = op( sum_k A[m,k]*B[n,k] (+bias) )
// BM=BN=64, BK=32, 128 threads, 2x2 warps, 32x32 warp tile.
// SPLIT: hi/lo tf32 decomposition (3 MMAs) => ~fp32 accuracy.
// Register-staged prefetch of next k-tile overlaps the MMA loop.
// ===========================================================================
template<int K, bool SPLIT, bool TANH>
__global__ void __launch_bounds__(128)
gemm_mma_k(const float* __restrict__ A, const float* __restrict__ Bm,
           const float* __restrict__ bias, float* __restrict__ C)
{
    constexpr int KW    = SPLIT ? 64 : 32;   // smem k-width (lo stored at +32)
    constexpr int PITCH = KW + 4;            // 36 or 68 -> 144B/272B rows, 16B-aligned
    constexpr int NKT   = K / 32;

    __shared__ uint32_t As[64][PITCH];
    __shared__ uint32_t Bs[64][PITCH];

    const int tid  = threadIdx.x;
    const int lane = tid & 31;
    const int warp = tid >> 5;        // 0..3
    const int wm   = warp >> 1;       // 0..1 -> m offset 32*wm
    const int wn   = warp & 1;        // 0..1 -> n offset 32*wn
    const int gid  = lane >> 2;       // 0..7
    const int tig  = lane & 3;        // 0..3

    const int m0 = blockIdx.y * 64;
    const int n0 = blockIdx.x * 64;

    // gmem tile load mapping: 64 rows x 8 float4-cols per matrix, 4 rows/thread
    const int lr = tid >> 3;          // 0..15
    const int lc = tid & 7;           // 0..7

    float c[2][4][4];
    #pragma unroll
    for (int i = 0; i < 2; i++)
        #pragma unroll
        for (int j = 0; j < 4; j++)
            #pragma unroll
            for (int q = 0; q < 4; q++) c[i][j][q] = 0.f;

    float4 pa[4], pb[4];

    auto load_tile = [&](int kk) {
        #pragma unroll
        for (int i = 0; i < 4; i++) {
            const int r = lr + i * 16;
            pa[i] = *(const float4*)(A  + (size_t)(m0 + r) * K + kk + lc * 4);
            pb[i] = *(const float4*)(Bm + (size_t)(n0 + r) * K + kk + lc * 4);
        }
    };
    auto store_tile = [&]() {
        #pragma unroll
        for (int i = 0; i < 4; i++) {
            const int r = lr + i * 16;
            if (SPLIT) {
                uint4 ah = make_uint4(f2tf32(pa[i].x), f2tf32(pa[i].y),
                                      f2tf32(pa[i].z), f2tf32(pa[i].w));
                uint4 bh = make_uint4(f2tf32(pb[i].x), f2tf32(pb[i].y),
                                      f2tf32(pb[i].z), f2tf32(pb[i].w));
                uint4 al = make_uint4(f2tf32(pa[i].x - __uint_as_float(ah.x)),
                                      f2tf32(pa[i].y - __uint_as_float(ah.y)),
                                      f2tf32(pa[i].z - __uint_as_float(ah.z)),
                                      f2tf32(pa[i].w - __uint_as_float(ah.w)));
                uint4 bl = make_uint4(f2tf32(pb[i].x - __uint_as_float(bh.x)),
                                      f2tf32(pb[i].y - __uint_as_float(bh.y)),
                                      f2tf32(pb[i].z - __uint_as_float(bh.z)),
                                      f2tf32(pb[i].w - __uint_as_float(bh.w)));
                *(uint4*)&As[r][lc * 4]      = ah;
                *(uint4*)&As[r][32 + lc * 4] = al;
                *(uint4*)&Bs[r][lc * 4]      = bh;
                *(uint4*)&Bs[r][32 + lc * 4] = bl;
            } else {
                *(uint4*)&As[r][lc * 4] = make_uint4(f2tf32(pa[i].x), f2tf32(pa[i].y),
                                                     f2tf32(pa[i].z), f2tf32(pa[i].w));
                *(uint4*)&Bs[r][lc * 4] = make_uint4(f2tf32(pb[i].x), f2tf32(pb[i].y),
                                                     f2tf32(pb[i].z), f2tf32(pb[i].w));
            }
        }
    };

    load_tile(0);
    store_tile();
    __syncthreads();

    for (int kt = 0; kt < NKT; kt++) {
        if (kt + 1 < NKT) load_tile((kt + 1) * 32);   // prefetch overlaps MMAs

        #pragma unroll
        for (int k8 = 0; k8 < 4; k8++) {
            const int k0 = k8 * 8;

            uint32_t af[2][4];
            #pragma unroll
            for (int mi = 0; mi < 2; mi++) {
                const int row = wm * 32 + mi * 16 + gid;
                af[mi][0] = As[row    ][k0 + tig];
                af[mi][1] = As[row + 8][k0 + tig];
                af[mi][2] = As[row    ][k0 + tig + 4];
                af[mi][3] = As[row + 8][k0 + tig + 4];
            }
            uint32_t bf[4][2];
            #pragma unroll
            for (int nj = 0; nj < 4; nj++) {
                const int col = wn * 32 + nj * 8 + gid;
                bf[nj][0] = Bs[col][k0 + tig];
                bf[nj][1] = Bs[col][k0 + tig + 4];
            }

            #define MMA(acc, a, b) \
                asm volatile( \
                    "mma.sync.aligned.m16n8k8.row.col.f32.tf32.tf32.f32 " \
                    "{%0,%1,%2,%3}, {%4,%5,%6,%7}, {%8,%9}, {%0,%1,%2,%3};" \
                    : "+f"((acc)[0]), "+f"((acc)[1]), "+f"((acc)[2]), "+f"((acc)[3]) \
                    : "r"((a)[0]), "r"((a)[1]), "r"((a)[2]), "r"((a)[3]), \
                      "r"((b)[0]), "r"((b)[1]))

            #pragma unroll
            for (int mi = 0; mi < 2; mi++)
                #pragma unroll
                for (int nj = 0; nj < 4; nj++)
                    MMA(c[mi][nj], af[mi], bf[nj]);

            if (SPLIT) {
                uint32_t afl[2][4];
                #pragma unroll
                for (int mi = 0; mi < 2; mi++) {
                    const int row = wm * 32 + mi * 16 + gid;
                    afl[mi][0] = As[row    ][32 + k0 + tig];
                    afl[mi][1] = As[row + 8][32 + k0 + tig];
                    afl[mi][2] = As[row    ][32 + k0 + tig + 4];
                    afl[mi][3] = As[row + 8][32 + k0 + tig + 4];
                }
                uint32_t bfl[4][2];
                #pragma unroll
                for (int nj = 0; nj < 4; nj++) {
                    const int col = wn * 32 + nj * 8 + gid;
                    bfl[nj][0] = Bs[col][32 + k0 + tig];
                    bfl[nj][1] = Bs[col][32 + k0 + tig + 4];
                }
                #pragma unroll
                for (int mi = 0; mi < 2; mi++)
                    #pragma unroll
                    for (int nj = 0; nj < 4; nj++) {
                        MMA(c[mi][nj], af[mi],  bfl[nj]);   // hi * lo
                        MMA(c[mi][nj], afl[mi], bf[nj]);    // lo * hi
                    }
            }
            #undef MMA
        }

        if (kt + 1 < NKT) {
            __syncthreads();
            store_tile();
            __syncthreads();
        }
    }

    // Epilogue: c0,c1 -> (row, 2tig..2tig+1); c2,c3 -> (row+8, same cols)
    #pragma unroll
    for (int mi = 0; mi < 2; mi++) {
        const int row = m0 + wm * 32 + mi * 16 + gid;
        #pragma unroll
        for (int nj = 0; nj < 4; nj++) {
            const int col = n0 + wn * 32 + nj * 8 + tig * 2;
            float v0 = c[mi][nj][0], v1 = c[mi][nj][1];
            float v2 = c[mi][nj][2], v3 = c[mi][nj][3];
            if (TANH) {
                const float b0 = bias[col], b1 = bias[col + 1];
                v0 = tanhf(v0 + b0); v1 = tanhf(v1 + b1);
                v2 = tanhf(v2 + b0); v3 = tanhf(v3 + b1);
            }
            *(float2*)(C + (size_t)row * DD + col)       = make_float2(v0, v1);
            *(float2*)(C + (size_t)(row + 8) * DD + col) = make_float2(v2, v3);
        }
    }
}

// ---------------------------------------------------------------------------
// Row-wise L2 normalize
// ---------------------------------------------------------------------------
__global__ void __launch_bounds__(256)
norm_rows_kernel(const float* __restrict__ in, float* __restrict__ out)
{
    const int b = blockIdx.x;
    const int t = threadIdx.x;
    const int lane = t & 31, warp = t >> 5;
    const float4* i4 = (const float4*)(in + (size_t)b * DD);
    float4 v = i4[t];
    float ss = v.x*v.x + v.y*v.y + v.z*v.z + v.w*v.w;
    #pragma unroll
    for (int o = 16; o; o >>= 1) ss += __shfl_xor_sync(0xffffffffu, ss, o);

    __shared__ float sred[8];
    __shared__ float sinv;
    if (lane == 0) sred[warp] = ss;
    __syncthreads();
    if (t == 0) {
        float tot = 0.f;
        #pragma unroll
        for (int w = 0; w < 8; w++) tot += sred[w];
        sinv = 1.0f / fmaxf(sqrtf(tot), 1e-12f);
    }
    __syncthreads();
    const float inv = sinv;
    float4* o4 = (float4*)(out + (size_t)b * DD);
    v.x *= inv; v.y *= inv; v.z *= inv; v.w *= inv;
    o4[t] = v;
}

// ---------------------------------------------------------------------------
// sims + argmax + gather (HBM-bound; reads 1 GB once)
// ---------------------------------------------------------------------------
__global__ void __launch_bounds__(256)
sims_argmax_kernel(const float* __restrict__ visual,
                   const float* __restrict__ tn,
                   float* __restrict__ vb)
{
    const int b = blockIdx.x;
    const int lane = threadIdx.x & 31;
    const int warp = threadIdx.x >> 5;

    const float4* v4 = (const float4*)(visual + (size_t)b * PP * DD);
    const float4* t4 = (const float4*)(tn + (size_t)b * DD);

    float4 tr[8];
    #pragma unroll
    for (int k = 0; k < 8; k++) tr[k] = t4[lane + 32 * k];

    float best = -1e30f; int bidx = 0; float bss = 1.f;

    for (int pp = 0; pp < 32; pp++) {
        const int p = warp * 32 + pp;
        const float4* row = v4 + (size_t)p * (DD / 4);
        float dot = 0.f, ss = 0.f;
        #pragma unroll
        for (int k = 0; k < 8; k++) {
            float4 v = row[lane + 32 * k];
            dot += v.x * tr[k].x + v.y * tr[k].y + v.z * tr[k].z + v.w * tr[k].w;
            ss  += v.x * v.x + v.y * v.y + v.z * v.z + v.w * v.w;
        }
        #pragma unroll
        for (int o = 16; o; o >>= 1) {
            dot += __shfl_xor_sync(0xffffffffu, dot, o);
            ss  += __shfl_xor_sync(0xffffffffu, ss,  o);
        }
        const float sim = dot / fmaxf(sqrtf(ss), 1e-12f);
        if (sim > best) { best = sim; bidx = p; bss = ss; }
    }

    __shared__ float sval[8]; __shared__ int sidx[8]; __shared__ float ssum[8];
    __shared__ int s_p; __shared__ float s_inv;
    if (lane == 0) { sval[warp] = best; sidx[warp] = bidx; ssum[warp] = bss; }
    __syncthreads();
    if (threadIdx.x == 0) {
        float bv = sval[0]; int bi = sidx[0]; float bs = ssum[0];
        #pragma unroll
        for (int w = 1; w < 8; w++) {
            if (sval[w] > bv || (sval[w] == bv && sidx[w] < bi)) {
                bv = sval[w]; bi = sidx[w]; bs = ssum[w];
            }
        }
        s_p = bi;
        s_inv = 1.0f / fmaxf(sqrtf(bs), 1e-12f);
    }
    __syncthreads();

    const int p = s_p;
    const float inv = s_inv;
    const float4* row = v4 + (size_t)p * (DD / 4);
    float4* ob = (float4*)(vb + (size_t)b * DD);
    for (int i = threadIdx.x; i < DD / 4; i += 256) {
        float4 v = row[i];
        v.x *= inv; v.y *= inv; v.z *= inv; v.w *= inv;
        ob[i] = v;
    }
}

// ---------------------------------------------------------------------------
extern "C" void kernel_launch(void* const* d_in, const int* in_sizes, int n_in,
                              void* d_out, int out_size)
{
    const float* visual = (const float*)d_in[0];   // [1024, 256, 1024]
    const float* text   = (const float*)d_in[1];   // [1024, 512]
    const float* W      = (const float*)d_in[2];   // [1024, 512]
    const float* bias   = (const float*)d_in[3];   // [1024]
    float* out = (float*)d_out;                    // [1024, 1024]

    float *p_t, *p_tn, *p_vb;
    cudaGetSymbolAddress((void**)&p_t,  g_t);
    cudaGetSymbolAddress((void**)&p_tn, g_tn);
    cudaGetSymbolAddress((void**)&p_vb, g_vb);

    // 1) t = tanh(text @ W^T + b)   (split-tf32: fp32-equivalent accuracy)
    gemm_mma_k<DC, true, true><<<dim3(16, 16), 128>>>(text, W, bias, p_t);
    // 2) tn = l2norm(t)
    norm_rows_kernel<<<BB, 256>>>(p_t, p_tn);
    // 3) per-b argmax over patches + gather normalized best patch
    sims_argmax_kernel<<<BB, 256>>>(visual, p_tn, p_vb);
    // 4) out = tn @ vb^T  (single-pass tf32)
    gemm_mma_k<DD, false, false><<<dim3(16, 16), 128>>>(p_tn, p_vb, nullptr, out);
}